// round 10
// baseline (speedup 1.0000x reference)
#include <cuda_runtime.h>

#define L_DIM 8192
#define B_DIM 4096
#define RANK 8
#define M_SPLITS 64
#define M_CHUNK (L_DIM / M_SPLITS)   // 128
#define B4 (B_DIM / 4)               // 1024 float4 lanes
#define L_TILE 128
#define NQ 4                          // b-quadrants

typedef unsigned long long u64;

__device__ __forceinline__ void fma2(u64& d, u64 a, u64 b) {
    asm("fma.rn.f32x2 %0, %1, %2, %0;" : "+l"(d) : "l"(a), "l"(b));
}
__device__ __forceinline__ u64 dup2(float v) {
    u64 r;
    asm("mov.b64 %0, {%1, %1};" : "=l"(r) : "f"(v));
    return r;
}
__device__ __forceinline__ u64 pack2(float x, float y) {
    u64 r;
    asm("mov.b64 %0, {%1, %2};" : "=l"(r) : "f"(x), "f"(y));
    return r;
}
__device__ __forceinline__ float2 unpk2(u64 a) {
    float2 f;
    asm("mov.b64 {%0, %1}, %2;" : "=f"(f.x), "=f"(f.y) : "l"(a));
    return f;
}

// T = V @ inputs -> [RANK, B]. Zero at load; re-zeroed by tail each launch.
__device__ float g_T[RANK * B_DIM];
// per-quadrant barrier state (zero-init; arrive resets each use, release monotonic)
__device__ int g_arrive[NQ];
__device__ int g_release[NQ];
// per-quadrant completion counters for the T-zeroing tail (self-resetting)
__device__ int g_count[NQ];

// grid (4, 64), block 256, 2 CTAs/SM: 256 CTAs all resident (capacity 296).
__global__ __launch_bounds__(256, 2) void fused_kernel(
    const float* __restrict__ inp, const float* __restrict__ U,
    const float* __restrict__ V, float* __restrict__ out) {
    __shared__ __align__(16) u64 s_w[RANK * M_CHUNK];  // 8 KB, Vs then Us
    __shared__ int s_go;

    const int t = threadIdx.x;
    const int q = blockIdx.x;                      // b-quadrant
    const int b4 = q * 256 + t;                    // 0..1023

    // ================= Phase 1: T += V(chunk) @ x(chunk) =================
    {
        u64* Vs = s_w;                             // [RANK][M_CHUNK]
        const int m0 = blockIdx.y * M_CHUNK;
        for (int i = t; i < RANK * M_CHUNK; i += blockDim.x) {
            int r = i >> 7;                        // / M_CHUNK
            int mi = i & (M_CHUNK - 1);
            Vs[r * M_CHUNK + mi] = dup2(V[r * L_DIM + m0 + mi]);
        }
        __syncthreads();

        const double2* in2 = (const double2*)inp;
        u64 acc[RANK][2];
        #pragma unroll
        for (int r = 0; r < RANK; r++) { acc[r][0] = 0ull; acc[r][1] = 0ull; }

        #pragma unroll 8
        for (int mi = 0; mi < M_CHUNK; mi++) {
            double2 x = __ldcs(&in2[(size_t)(m0 + mi) * B4 + b4]);
            u64 xlo = (u64)__double_as_longlong(x.x);
            u64 xhi = (u64)__double_as_longlong(x.y);
            #pragma unroll
            for (int r = 0; r < RANK; r++) {
                u64 v2 = Vs[r * M_CHUNK + mi];
                fma2(acc[r][0], v2, xlo);
                fma2(acc[r][1], v2, xhi);
            }
        }

        const int b = b4 * 4;
        #pragma unroll
        for (int r = 0; r < RANK; r++) {
            float2 lo = unpk2(acc[r][0]);
            float2 hi = unpk2(acc[r][1]);
            float* dst = &g_T[r * B_DIM + b];
            atomicAdd(dst + 0, lo.x);
            atomicAdd(dst + 1, lo.y);
            atomicAdd(dst + 2, hi.x);
            atomicAdd(dst + 3, hi.y);
        }
    }

    // ============ per-quadrant barrier: wait for this quadrant's T ============
    __threadfence();
    __syncthreads();                 // all warps' atomics issued before arrive
    if (t == 0) {
        int epoch = atomicAdd(&g_release[q], 0);
        int a = atomicAdd(&g_arrive[q], 1);
        if (a == (int)gridDim.y - 1) {
            atomicExch(&g_arrive[q], 0);
            __threadfence();
            atomicAdd(&g_release[q], 1);        // release (monotonic)
        } else {
            while (atomicAdd(&g_release[q], 0) == epoch) __nanosleep(64);
        }
        s_go = 1;
    }
    __syncthreads();
    __threadfence();

    // ================= Phase 2: out tile (q, blockIdx.y) =================
    {
        u64* Us = s_w;                             // [L_TILE][RANK]
        const int l0 = blockIdx.y * L_TILE;
        for (int i = t; i < RANK * L_TILE; i += blockDim.x) {
            int li = i >> 3;
            int r = i & 7;
            Us[li * RANK + r] = dup2(U[r * L_DIM + l0 + li]);
        }
        __syncthreads();

        const float4* T4 = (const float4*)g_T;
        u64 tld[RANK][2];
        #pragma unroll
        for (int r = 0; r < RANK; r++) {
            float4 v = __ldg(&T4[r * B4 + b4]);
            tld[r][0] = pack2(v.x, v.y);
            tld[r][1] = pack2(v.z, v.w);
        }

        float4* out4 = (float4*)out;
        #pragma unroll 4
        for (int li = 0; li < L_TILE; li++) {
            const ulonglong2* up = (const ulonglong2*)&Us[li * RANK];
            ulonglong2 u01 = up[0], u23 = up[1], u45 = up[2], u67 = up[3];
            u64 a0 = 0ull, a1 = 0ull;
            fma2(a0, u01.x, tld[0][0]); fma2(a1, u01.x, tld[0][1]);
            fma2(a0, u01.y, tld[1][0]); fma2(a1, u01.y, tld[1][1]);
            fma2(a0, u23.x, tld[2][0]); fma2(a1, u23.x, tld[2][1]);
            fma2(a0, u23.y, tld[3][0]); fma2(a1, u23.y, tld[3][1]);
            fma2(a0, u45.x, tld[4][0]); fma2(a1, u45.x, tld[4][1]);
            fma2(a0, u45.y, tld[5][0]); fma2(a1, u45.y, tld[5][1]);
            fma2(a0, u67.x, tld[6][0]); fma2(a1, u67.x, tld[6][1]);
            fma2(a0, u67.y, tld[7][0]); fma2(a1, u67.y, tld[7][1]);
            float2 lo = unpk2(a0);
            float2 hi = unpk2(a1);
            __stcs(&out4[(size_t)(l0 + li) * B4 + b4],
                   make_float4(lo.x, lo.y, hi.x, hi.y));
        }
    }

    // ===== tail: last CTA of this quadrant re-zeroes its T slice + counter =====
    __syncthreads();
    __threadfence();
    if (t == 0) {
        int old = atomicAdd(&g_count[q], 1);
        s_go = (old == (int)gridDim.y - 1);
    }
    __syncthreads();
    if (s_go) {
        float4 z = make_float4(0.f, 0.f, 0.f, 0.f);
        float4* Tz = (float4*)g_T;
        #pragma unroll
        for (int r = 0; r < RANK; r++)
            Tz[r * B4 + b4] = z;
        __threadfence();
        if (t == 0) atomicExch(&g_count[q], 0);
    }
}

extern "C" void kernel_launch(void* const* d_in, const int* in_sizes, int n_in,
                              void* d_out, int out_size) {
    const float* inp = (const float*)d_in[0];  // [L, B]
    const float* U   = (const float*)d_in[1];  // [RANK, L]
    const float* V   = (const float*)d_in[2];  // [RANK, L]
    float* out = (float*)d_out;                // [L, B]

    dim3 g(NQ, M_SPLITS);                      // 256 CTAs, all resident
    fused_kernel<<<g, 256>>>(inp, U, V, out);
}

// round 11
// speedup vs baseline: 1.0666x; 1.0666x over previous
#include <cuda_runtime.h>

#define L_DIM 8192
#define B_DIM 4096
#define RANK 8
#define M_SPLITS 64
#define M_CHUNK (L_DIM / M_SPLITS)   // 128
#define B4 (B_DIM / 4)               // 1024 float4 lanes
#define L_TILE 128

typedef unsigned long long u64;

__device__ __forceinline__ void fma2(u64& d, u64 a, u64 b) {
    asm("fma.rn.f32x2 %0, %1, %2, %0;" : "+l"(d) : "l"(a), "l"(b));
}
__device__ __forceinline__ u64 dup2(float v) {
    u64 r;
    asm("mov.b64 %0, {%1, %1};" : "=l"(r) : "f"(v));
    return r;
}
__device__ __forceinline__ u64 pack2(float x, float y) {
    u64 r;
    asm("mov.b64 %0, {%1, %2};" : "=l"(r) : "f"(x), "f"(y));
    return r;
}
__device__ __forceinline__ float2 unpk2(u64 a) {
    float2 f;
    asm("mov.b64 {%0, %1}, %2;" : "=f"(f.x), "=f"(f.y) : "l"(a));
    return f;
}

// T = V @ inputs -> [RANK, B]. Zero-initialized at load; re-zeroed by out_kernel
// tail each launch, so every kernel_launch call starts from T == 0.
__device__ float g_T[RANK * B_DIM];
// per-b-quadrant completion counters for out_kernel (zero-init, self-resetting)
__device__ int g_count[4];

// stage 1: g_T[r, b] += sum_{m in chunk s} V[r, m] * inputs[m, b]  (RED.F32)
// rank-pair packing: multiplier pair = (v_{2rp}, v_{2rp+1}) straight from smem,
// x duplicated per b-column on the ALU pipe. 2 LDS.128 per mi (was 8 LDS.64).
// grid: (B4/256 = 4, M_SPLITS = 64), block: 256, 2 CTAs/SM
__global__ __launch_bounds__(256, 2) void vx_kernel(
    const float* __restrict__ inp, const float* __restrict__ V) {
    __shared__ __align__(16) float Vs[M_CHUNK][RANK];   // compact, 4 KB

    const int s = blockIdx.y;
    const int m0 = s * M_CHUNK;
    for (int i = threadIdx.x; i < RANK * M_CHUNK; i += blockDim.x) {
        int r = i >> 7;               // / M_CHUNK  (coalesced global read)
        int mi = i & (M_CHUNK - 1);
        Vs[mi][r] = V[r * L_DIM + m0 + mi];
    }
    __syncthreads();

    const int b4 = blockIdx.x * blockDim.x + threadIdx.x;  // 0..1023
    const float4* in4 = (const float4*)inp;

    // acc[rp][b] = packed (T[2rp][b], T[2rp+1][b]) partial for b-column b
    u64 acc[4][4];
    #pragma unroll
    for (int rp = 0; rp < 4; rp++)
        #pragma unroll
        for (int b = 0; b < 4; b++) acc[rp][b] = 0ull;

    #pragma unroll 8
    for (int mi = 0; mi < M_CHUNK; mi++) {
        float4 x = __ldcs(&in4[(size_t)(m0 + mi) * B4 + b4]);
        u64 xd[4];
        xd[0] = dup2(x.x); xd[1] = dup2(x.y);
        xd[2] = dup2(x.z); xd[3] = dup2(x.w);
        const ulonglong2* vp = (const ulonglong2*)&Vs[mi][0];
        ulonglong2 v01_23 = vp[0];    // LDS.128 broadcast: (v0,v1),(v2,v3)
        ulonglong2 v45_67 = vp[1];    // LDS.128 broadcast: (v4,v5),(v6,v7)
        u64 vpair[4] = { v01_23.x, v01_23.y, v45_67.x, v45_67.y };
        #pragma unroll
        for (int rp = 0; rp < 4; rp++) {
            fma2(acc[rp][0], vpair[rp], xd[0]);
            fma2(acc[rp][1], vpair[rp], xd[1]);
            fma2(acc[rp][2], vpair[rp], xd[2]);
            fma2(acc[rp][3], vpair[rp], xd[3]);
        }
    }

    const int b = b4 * 4;
    #pragma unroll
    for (int rp = 0; rp < 4; rp++) {
        #pragma unroll
        for (int bc = 0; bc < 4; bc++) {
            float2 p = unpk2(acc[rp][bc]);
            atomicAdd(&g_T[(2 * rp + 0) * B_DIM + b + bc], p.x);
            atomicAdd(&g_T[(2 * rp + 1) * B_DIM + b + bc], p.y);
        }
    }
}

// stage 2: out[l, b] = sum_r U[r, l] * T[r, b]; tail re-zeroes T for next launch
// grid: (B4/256 = 4, L_DIM / L_TILE = 64), block: 256, 2 CTAs/SM (no spill)
__global__ __launch_bounds__(256, 2) void out_kernel(
    const float* __restrict__ U, float* __restrict__ out) {
    __shared__ __align__(16) u64 Us[L_TILE][RANK];  // transposed, dup pairs, 8 KB
    __shared__ int s_last;

    const int t = threadIdx.x;
    const int l0 = blockIdx.y * L_TILE;
    for (int i = t; i < RANK * L_TILE; i += blockDim.x) {
        int li = i >> 3;
        int r = i & 7;
        Us[li][r] = dup2(U[r * L_DIM + l0 + li]);
    }
    __syncthreads();

    const int b4 = blockIdx.x * blockDim.x + t;  // 0..1023
    const float4* T4 = (const float4*)g_T;

    u64 tld[RANK][2];
    #pragma unroll
    for (int r = 0; r < RANK; r++) {
        float4 v = __ldg(&T4[r * B4 + b4]);
        tld[r][0] = pack2(v.x, v.y);
        tld[r][1] = pack2(v.z, v.w);
    }

    float4* out4 = (float4*)out;
    #pragma unroll 4
    for (int li = 0; li < L_TILE; li++) {
        // 4x LDS.128 (broadcast) for the 8 rank operands of this li
        const ulonglong2* up = (const ulonglong2*)&Us[li][0];
        ulonglong2 u01 = up[0], u23 = up[1], u45 = up[2], u67 = up[3];
        u64 a0 = 0ull, a1 = 0ull;
        fma2(a0, u01.x, tld[0][0]); fma2(a1, u01.x, tld[0][1]);
        fma2(a0, u01.y, tld[1][0]); fma2(a1, u01.y, tld[1][1]);
        fma2(a0, u23.x, tld[2][0]); fma2(a1, u23.x, tld[2][1]);
        fma2(a0, u23.y, tld[3][0]); fma2(a1, u23.y, tld[3][1]);
        fma2(a0, u45.x, tld[4][0]); fma2(a1, u45.x, tld[4][1]);
        fma2(a0, u45.y, tld[5][0]); fma2(a1, u45.y, tld[5][1]);
        fma2(a0, u67.x, tld[6][0]); fma2(a1, u67.x, tld[6][1]);
        fma2(a0, u67.y, tld[7][0]); fma2(a1, u67.y, tld[7][1]);
        float2 lo = unpk2(a0);
        float2 hi = unpk2(a1);
        __stcs(&out4[(size_t)(l0 + li) * B4 + b4],
               make_float4(lo.x, lo.y, hi.x, hi.y));
    }

    // --- tail: last CTA of this b-quadrant re-zeroes its T slice + counter ---
    __syncthreads();
    __threadfence();
    if (t == 0) {
        int old = atomicAdd(&g_count[blockIdx.x], 1);
        s_last = (old == (int)gridDim.y - 1);
    }
    __syncthreads();
    if (s_last) {
        float4 z = make_float4(0.f, 0.f, 0.f, 0.f);
        float4* Tz = (float4*)g_T;
        #pragma unroll
        for (int r = 0; r < RANK; r++)
            Tz[r * B4 + b4] = z;
        __threadfence();
        if (t == 0) atomicExch(&g_count[blockIdx.x], 0);
    }
}

extern "C" void kernel_launch(void* const* d_in, const int* in_sizes, int n_in,
                              void* d_out, int out_size) {
    const float* inp = (const float*)d_in[0];  // [L, B]
    const float* U   = (const float*)d_in[1];  // [RANK, L]
    const float* V   = (const float*)d_in[2];  // [RANK, L]
    float* out = (float*)d_out;                // [L, B]

    dim3 g1(B4 / 256, M_SPLITS);
    vx_kernel<<<g1, 256>>>(inp, V);

    dim3 g2(B4 / 256, L_DIM / L_TILE);
    out_kernel<<<g2, 256>>>(U, out);
}

// round 12
// speedup vs baseline: 1.0671x; 1.0005x over previous
#include <cuda_runtime.h>

#define L_DIM 8192
#define B_DIM 4096
#define RANK 8
#define M_SPLITS 64
#define M_CHUNK (L_DIM / M_SPLITS)   // 128
#define B4 (B_DIM / 4)               // 1024 float4 lanes
#define L_TILE 128

typedef unsigned long long u64;

__device__ __forceinline__ void fma2(u64& d, u64 a, u64 b) {
    asm("fma.rn.f32x2 %0, %1, %2, %0;" : "+l"(d) : "l"(a), "l"(b));
}
__device__ __forceinline__ u64 dup2(float v) {
    u64 r;
    asm("mov.b64 %0, {%1, %1};" : "=l"(r) : "f"(v));
    return r;
}
__device__ __forceinline__ u64 pack2(float x, float y) {
    u64 r;
    asm("mov.b64 %0, {%1, %2};" : "=l"(r) : "f"(x), "f"(y));
    return r;
}
__device__ __forceinline__ float2 unpk2(u64 a) {
    float2 f;
    asm("mov.b64 {%0, %1}, %2;" : "=f"(f.x), "=f"(f.y) : "l"(a));
    return f;
}

// T = V @ inputs -> [RANK, B]. Zero-initialized at load; re-zeroed by out_kernel
// tail each launch, so every kernel_launch call starts from T == 0.
__device__ float g_T[RANK * B_DIM];
// per-b-quadrant completion counters for out_kernel (zero-init, self-resetting)
__device__ int g_count[4];

// stage 1: g_T[r, b] += sum_{m in chunk s} V[r, m] * inputs[m, b]  (RED.F32)
// grid: (B4/256 = 4, M_SPLITS = 64), block: 256, 2 CTAs/SM
__global__ __launch_bounds__(256, 2) void vx_kernel(
    const float* __restrict__ inp, const float* __restrict__ V) {
    __shared__ u64 Vs[RANK][M_CHUNK];   // duplicated pairs, 8 KB

    const int s = blockIdx.y;
    const int m0 = s * M_CHUNK;
    for (int i = threadIdx.x; i < RANK * M_CHUNK; i += blockDim.x) {
        int r = i >> 7;               // / M_CHUNK
        int mi = i & (M_CHUNK - 1);
        Vs[r][mi] = dup2(V[r * L_DIM + m0 + mi]);
    }
    __syncthreads();

    const int b4 = blockIdx.x * blockDim.x + threadIdx.x;  // 0..1023
    const double2* in2 = (const double2*)inp;   // float4 as 2x u64 halves

    u64 acc[RANK][2];
    #pragma unroll
    for (int r = 0; r < RANK; r++) { acc[r][0] = 0ull; acc[r][1] = 0ull; }

    #pragma unroll 8
    for (int mi = 0; mi < M_CHUNK; mi++) {
        double2 x = __ldcs(&in2[(size_t)(m0 + mi) * B4 + b4]);
        u64 xlo = (u64)__double_as_longlong(x.x);
        u64 xhi = (u64)__double_as_longlong(x.y);
        #pragma unroll
        for (int r = 0; r < RANK; r++) {
            u64 v2 = Vs[r][mi];
            fma2(acc[r][0], v2, xlo);
            fma2(acc[r][1], v2, xhi);
        }
    }

    const int b = b4 * 4;
    #pragma unroll
    for (int r = 0; r < RANK; r++) {
        float2 lo = unpk2(acc[r][0]);
        float2 hi = unpk2(acc[r][1]);
        float* dst = &g_T[r * B_DIM + b];
        atomicAdd(dst + 0, lo.x);
        atomicAdd(dst + 1, lo.y);
        atomicAdd(dst + 2, hi.x);
        atomicAdd(dst + 3, hi.y);
    }
}

// stage 2: out[l, b] = sum_r U[r, l] * T[r, b]; tail re-zeroes T for next launch
// Rank-pair form: U stored compact (no dup) -> 2 LDS.128 per li; T held as
// rank-pair packs; 4 fma2 + 1 horizontal add per output column.
// grid: (B4/256 = 4, L_DIM / L_TILE = 64), block: 256, 2 CTAs/SM
__global__ __launch_bounds__(256, 2) void out_kernel(
    const float* __restrict__ U, float* __restrict__ out) {
    __shared__ __align__(16) float Us[L_TILE][RANK];  // compact, 4 KB
    __shared__ int s_last;

    const int t = threadIdx.x;
    const int l0 = blockIdx.y * L_TILE;
    for (int i = t; i < RANK * L_TILE; i += blockDim.x) {
        int r = i >> 7;               // / L_TILE  (coalesced global read)
        int li = i & (L_TILE - 1);
        Us[li][r] = U[r * L_DIM + l0 + li];
    }
    __syncthreads();

    const int b4 = blockIdx.x * blockDim.x + t;  // 0..1023
    const float4* T4 = (const float4*)g_T;

    // tp[rp][c] = packed (T[2rp][col c], T[2rp+1][col c])
    u64 tp[4][4];
    {
        float4 v[RANK];
        #pragma unroll
        for (int r = 0; r < RANK; r++) v[r] = __ldg(&T4[r * B4 + b4]);
        #pragma unroll
        for (int rp = 0; rp < 4; rp++) {
            tp[rp][0] = pack2(v[2 * rp].x, v[2 * rp + 1].x);
            tp[rp][1] = pack2(v[2 * rp].y, v[2 * rp + 1].y);
            tp[rp][2] = pack2(v[2 * rp].z, v[2 * rp + 1].z);
            tp[rp][3] = pack2(v[2 * rp].w, v[2 * rp + 1].w);
        }
    }

    float4* out4 = (float4*)out;
    #pragma unroll 4
    for (int li = 0; li < L_TILE; li++) {
        // 2x LDS.128 broadcast: natural rank pairs (u0,u1)(u2,u3) / (u4,u5)(u6,u7)
        const ulonglong2* up = (const ulonglong2*)&Us[li][0];
        ulonglong2 ua = up[0];
        ulonglong2 ub = up[1];
        float o[4];
        #pragma unroll
        for (int c = 0; c < 4; c++) {
            u64 acc = 0ull;
            fma2(acc, ua.x, tp[0][c]);
            fma2(acc, ua.y, tp[1][c]);
            fma2(acc, ub.x, tp[2][c]);
            fma2(acc, ub.y, tp[3][c]);
            float2 p = unpk2(acc);
            o[c] = __fadd_rn(p.x, p.y);
        }
        __stcs(&out4[(size_t)(l0 + li) * B4 + b4],
               make_float4(o[0], o[1], o[2], o[3]));
    }

    // --- tail: last CTA of this b-quadrant re-zeroes its T slice + counter ---
    __syncthreads();
    __threadfence();
    if (t == 0) {
        int old = atomicAdd(&g_count[blockIdx.x], 1);
        s_last = (old == (int)gridDim.y - 1);
    }
    __syncthreads();
    if (s_last) {
        float4 z = make_float4(0.f, 0.f, 0.f, 0.f);
        float4* Tz = (float4*)g_T;
        #pragma unroll
        for (int r = 0; r < RANK; r++)
            Tz[r * B4 + b4] = z;
        __threadfence();
        if (t == 0) atomicExch(&g_count[blockIdx.x], 0);
    }
}

extern "C" void kernel_launch(void* const* d_in, const int* in_sizes, int n_in,
                              void* d_out, int out_size) {
    const float* inp = (const float*)d_in[0];  // [L, B]
    const float* U   = (const float*)d_in[1];  // [RANK, L]
    const float* V   = (const float*)d_in[2];  // [RANK, L]
    float* out = (float*)d_out;                // [L, B]

    dim3 g1(B4 / 256, M_SPLITS);
    vx_kernel<<<g1, 256>>>(inp, V);

    dim3 g2(B4 / 256, L_DIM / L_TILE);
    out_kernel<<<g2, 256>>>(U, out);
}

// round 13
// speedup vs baseline: 1.1452x; 1.0732x over previous
#include <cuda_runtime.h>

#define L_DIM 8192
#define B_DIM 4096
#define RANK 8
#define M_SPLITS 64
#define M_CHUNK (L_DIM / M_SPLITS)   // 128
#define B4 (B_DIM / 4)               // 1024 float4 lanes
#define L_TILE 128

typedef unsigned long long u64;

__device__ __forceinline__ void fma2(u64& d, u64 a, u64 b) {
    asm("fma.rn.f32x2 %0, %1, %2, %0;" : "+l"(d) : "l"(a), "l"(b));
}
__device__ __forceinline__ u64 dup2(float v) {
    u64 r;
    asm("mov.b64 %0, {%1, %1};" : "=l"(r) : "f"(v));
    return r;
}
__device__ __forceinline__ u64 pack2(float x, float y) {
    u64 r;
    asm("mov.b64 %0, {%1, %2};" : "=l"(r) : "f"(x), "f"(y));
    return r;
}
__device__ __forceinline__ float2 unpk2(u64 a) {
    float2 f;
    asm("mov.b64 {%0, %1}, %2;" : "=f"(f.x), "=f"(f.y) : "l"(a));
    return f;
}
__device__ __forceinline__ void red_add_v4(float* p, float a, float b,
                                           float c, float d) {
    asm volatile("red.global.add.v4.f32 [%0], {%1, %2, %3, %4};"
                 :: "l"(p), "f"(a), "f"(b), "f"(c), "f"(d) : "memory");
}

// T = V @ inputs -> [RANK, B]. Zero-initialized at load; re-zeroed by out_kernel
// tail each launch, so every kernel_launch call starts from T == 0.
__device__ float g_T[RANK * B_DIM];
// per-b-quadrant completion counters for out_kernel (zero-init, self-resetting)
__device__ int g_count[4];

// stage 1: g_T[r, b] += sum_{m in chunk s} V[r, m] * inputs[m, b]  (RED.v4)
// grid: (B4/256 = 4, M_SPLITS = 64), block: 256, 2 CTAs/SM
__global__ __launch_bounds__(256, 2) void vx_kernel(
    const float* __restrict__ inp, const float* __restrict__ V) {
    __shared__ u64 Vs[RANK][M_CHUNK];   // duplicated pairs, 8 KB

    const int s = blockIdx.y;
    const int m0 = s * M_CHUNK;
    for (int i = threadIdx.x; i < RANK * M_CHUNK; i += blockDim.x) {
        int r = i >> 7;               // / M_CHUNK
        int mi = i & (M_CHUNK - 1);
        Vs[r][mi] = dup2(V[r * L_DIM + m0 + mi]);
    }
    __syncthreads();

    const int b4 = blockIdx.x * blockDim.x + threadIdx.x;  // 0..1023
    const double2* in2 = (const double2*)inp;   // float4 as 2x u64 halves

    u64 acc[RANK][2];
    #pragma unroll
    for (int r = 0; r < RANK; r++) { acc[r][0] = 0ull; acc[r][1] = 0ull; }

    #pragma unroll 8
    for (int mi = 0; mi < M_CHUNK; mi++) {
        double2 x = __ldcs(&in2[(size_t)(m0 + mi) * B4 + b4]);
        u64 xlo = (u64)__double_as_longlong(x.x);
        u64 xhi = (u64)__double_as_longlong(x.y);
        #pragma unroll
        for (int r = 0; r < RANK; r++) {
            u64 v2 = Vs[r][mi];
            fma2(acc[r][0], v2, xlo);
            fma2(acc[r][1], v2, xhi);
        }
    }

    const int b = b4 * 4;
    #pragma unroll
    for (int r = 0; r < RANK; r++) {
        float2 lo = unpk2(acc[r][0]);
        float2 hi = unpk2(acc[r][1]);
        red_add_v4(&g_T[r * B_DIM + b], lo.x, lo.y, hi.x, hi.y);
    }
}

// stage 2: out[l, b] = sum_r U[r, l] * T[r, b]; tail re-zeroes T for next launch
// Rank-pair form: U compact -> 2 LDS.128 per li; T as rank-pair packs.
// grid: (B4/256 = 4, L_DIM / L_TILE = 64), block: 256, 3 CTAs/SM (74 regs fit)
__global__ __launch_bounds__(256, 3) void out_kernel(
    const float* __restrict__ U, float* __restrict__ out) {
    __shared__ __align__(16) float Us[L_TILE][RANK];  // compact, 4 KB
    __shared__ int s_last;

    const int t = threadIdx.x;
    const int l0 = blockIdx.y * L_TILE;
    for (int i = t; i < RANK * L_TILE; i += blockDim.x) {
        int r = i >> 7;               // / L_TILE  (coalesced global read)
        int li = i & (L_TILE - 1);
        Us[li][r] = U[r * L_DIM + l0 + li];
    }
    __syncthreads();

    const int b4 = blockIdx.x * blockDim.x + t;  // 0..1023
    const float4* T4 = (const float4*)g_T;

    // tp[rp][c] = packed (T[2rp][col c], T[2rp+1][col c])
    u64 tp[4][4];
    {
        float4 v[RANK];
        #pragma unroll
        for (int r = 0; r < RANK; r++) v[r] = __ldg(&T4[r * B4 + b4]);
        #pragma unroll
        for (int rp = 0; rp < 4; rp++) {
            tp[rp][0] = pack2(v[2 * rp].x, v[2 * rp + 1].x);
            tp[rp][1] = pack2(v[2 * rp].y, v[2 * rp + 1].y);
            tp[rp][2] = pack2(v[2 * rp].z, v[2 * rp + 1].z);
            tp[rp][3] = pack2(v[2 * rp].w, v[2 * rp + 1].w);
        }
    }

    float4* out4 = (float4*)out;
    #pragma unroll 4
    for (int li = 0; li < L_TILE; li++) {
        // 2x LDS.128 broadcast: natural rank pairs (u0,u1)(u2,u3) / (u4,u5)(u6,u7)
        const ulonglong2* up = (const ulonglong2*)&Us[li][0];
        ulonglong2 ua = up[0];
        ulonglong2 ub = up[1];
        float o[4];
        #pragma unroll
        for (int c = 0; c < 4; c++) {
            u64 acc = 0ull;
            fma2(acc, ua.x, tp[0][c]);
            fma2(acc, ua.y, tp[1][c]);
            fma2(acc, ub.x, tp[2][c]);
            fma2(acc, ub.y, tp[3][c]);
            float2 p = unpk2(acc);
            o[c] = __fadd_rn(p.x, p.y);
        }
        __stcs(&out4[(size_t)(l0 + li) * B4 + b4],
               make_float4(o[0], o[1], o[2], o[3]));
    }

    // --- tail: last CTA of this b-quadrant re-zeroes its T slice + counter ---
    __syncthreads();
    __threadfence();
    if (t == 0) {
        int old = atomicAdd(&g_count[blockIdx.x], 1);
        s_last = (old == (int)gridDim.y - 1);
    }
    __syncthreads();
    if (s_last) {
        float4 z = make_float4(0.f, 0.f, 0.f, 0.f);
        float4* Tz = (float4*)g_T;
        #pragma unroll
        for (int r = 0; r < RANK; r++)
            Tz[r * B4 + b4] = z;
        __threadfence();
        if (t == 0) atomicExch(&g_count[blockIdx.x], 0);
    }
}

extern "C" void kernel_launch(void* const* d_in, const int* in_sizes, int n_in,
                              void* d_out, int out_size) {
    const float* inp = (const float*)d_in[0];  // [L, B]
    const float* U   = (const float*)d_in[1];  // [RANK, L]
    const float* V   = (const float*)d_in[2];  // [RANK, L]
    float* out = (float*)d_out;                // [L, B]

    dim3 g1(B4 / 256, M_SPLITS);
    vx_kernel<<<g1, 256>>>(inp, V);

    dim3 g2(B4 / 256, L_DIM / L_TILE);
    out_kernel<<<g2, 256>>>(U, out);
}

// round 14
// speedup vs baseline: 1.1503x; 1.0045x over previous
#include <cuda_runtime.h>

#define L_DIM 8192
#define B_DIM 4096
#define RANK 8
#define M_SPLITS 64
#define M_CHUNK (L_DIM / M_SPLITS)   // 128
#define B4 (B_DIM / 4)               // 1024 float4 lanes
#define L_TILE 64

typedef unsigned long long u64;

__device__ __forceinline__ void fma2(u64& d, u64 a, u64 b) {
    asm("fma.rn.f32x2 %0, %1, %2, %0;" : "+l"(d) : "l"(a), "l"(b));
}
__device__ __forceinline__ u64 dup2(float v) {
    u64 r;
    asm("mov.b64 %0, {%1, %1};" : "=l"(r) : "f"(v));
    return r;
}
__device__ __forceinline__ u64 pack2(float x, float y) {
    u64 r;
    asm("mov.b64 %0, {%1, %2};" : "=l"(r) : "f"(x), "f"(y));
    return r;
}
__device__ __forceinline__ float2 unpk2(u64 a) {
    float2 f;
    asm("mov.b64 {%0, %1}, %2;" : "=f"(f.x), "=f"(f.y) : "l"(a));
    return f;
}
__device__ __forceinline__ void red_add_v4(float* p, float a, float b,
                                           float c, float d) {
    asm volatile("red.global.add.v4.f32 [%0], {%1, %2, %3, %4};"
                 :: "l"(p), "f"(a), "f"(b), "f"(c), "f"(d) : "memory");
}

// T = V @ inputs -> [RANK, B]. Zero-initialized at load; re-zeroed by out_kernel
// tail each launch, so every kernel_launch call starts from T == 0.
__device__ float g_T[RANK * B_DIM];
// per-b-quadrant completion counters for out_kernel (zero-init, self-resetting)
__device__ int g_count[4];

// stage 1: g_T[r, b] += sum_{m in chunk s} V[r, m] * inputs[m, b]  (RED.v4)
// grid: (B4/256 = 4, M_SPLITS = 64), block: 256, 2 CTAs/SM
__global__ __launch_bounds__(256, 2) void vx_kernel(
    const float* __restrict__ inp, const float* __restrict__ V) {
    __shared__ u64 Vs[RANK][M_CHUNK];   // duplicated pairs, 8 KB

    const int s = blockIdx.y;
    const int m0 = s * M_CHUNK;
    for (int i = threadIdx.x; i < RANK * M_CHUNK; i += blockDim.x) {
        int r = i >> 7;               // / M_CHUNK
        int mi = i & (M_CHUNK - 1);
        Vs[r][mi] = dup2(V[r * L_DIM + m0 + mi]);
    }
    __syncthreads();

    const int b4 = blockIdx.x * blockDim.x + threadIdx.x;  // 0..1023
    const double2* in2 = (const double2*)inp;   // float4 as 2x u64 halves

    u64 acc[RANK][2];
    #pragma unroll
    for (int r = 0; r < RANK; r++) { acc[r][0] = 0ull; acc[r][1] = 0ull; }

    #pragma unroll 8
    for (int mi = 0; mi < M_CHUNK; mi++) {
        double2 x = __ldcs(&in2[(size_t)(m0 + mi) * B4 + b4]);
        u64 xlo = (u64)__double_as_longlong(x.x);
        u64 xhi = (u64)__double_as_longlong(x.y);
        #pragma unroll
        for (int r = 0; r < RANK; r++) {
            u64 v2 = Vs[r][mi];
            fma2(acc[r][0], v2, xlo);
            fma2(acc[r][1], v2, xhi);
        }
    }

    const int b = b4 * 4;
    #pragma unroll
    for (int r = 0; r < RANK; r++) {
        float2 lo = unpk2(acc[r][0]);
        float2 hi = unpk2(acc[r][1]);
        red_add_v4(&g_T[r * B_DIM + b], lo.x, lo.y, hi.x, hi.y);
    }
}

// stage 2: out[l, b] = sum_r U[r, l] * T[r, b]; tail re-zeroes T for next launch
// Rank-pair form: U compact -> 2 LDS.128 per li; T as rank-pair packs.
// grid: (B4/256 = 4, L_DIM / L_TILE = 128), block: 256, 3 CTAs/SM (74 regs)
__global__ __launch_bounds__(256, 3) void out_kernel(
    const float* __restrict__ U, float* __restrict__ out) {
    __shared__ __align__(16) float Us[L_TILE][RANK];  // compact, 2 KB
    __shared__ int s_last;

    const int t = threadIdx.x;
    const int l0 = blockIdx.y * L_TILE;
    for (int i = t; i < RANK * L_TILE; i += blockDim.x) {
        int r = i >> 6;               // / L_TILE  (coalesced global read)
        int li = i & (L_TILE - 1);
        Us[li][r] = U[r * L_DIM + l0 + li];
    }
    __syncthreads();

    const int b4 = blockIdx.x * blockDim.x + t;  // 0..1023
    const float4* T4 = (const float4*)g_T;

    // tp[rp][c] = packed (T[2rp][col c], T[2rp+1][col c])
    u64 tp[4][4];
    {
        float4 v[RANK];
        #pragma unroll
        for (int r = 0; r < RANK; r++) v[r] = __ldg(&T4[r * B4 + b4]);
        #pragma unroll
        for (int rp = 0; rp < 4; rp++) {
            tp[rp][0] = pack2(v[2 * rp].x, v[2 * rp + 1].x);
            tp[rp][1] = pack2(v[2 * rp].y, v[2 * rp + 1].y);
            tp[rp][2] = pack2(v[2 * rp].z, v[2 * rp + 1].z);
            tp[rp][3] = pack2(v[2 * rp].w, v[2 * rp + 1].w);
        }
    }

    float4* out4 = (float4*)out;
    #pragma unroll 4
    for (int li = 0; li < L_TILE; li++) {
        // 2x LDS.128 broadcast: natural rank pairs (u0,u1)(u2,u3) / (u4,u5)(u6,u7)
        const ulonglong2* up = (const ulonglong2*)&Us[li][0];
        ulonglong2 ua = up[0];
        ulonglong2 ub = up[1];
        float o[4];
        #pragma unroll
        for (int c = 0; c < 4; c++) {
            u64 acc = 0ull;
            fma2(acc, ua.x, tp[0][c]);
            fma2(acc, ua.y, tp[1][c]);
            fma2(acc, ub.x, tp[2][c]);
            fma2(acc, ub.y, tp[3][c]);
            float2 p = unpk2(acc);
            o[c] = __fadd_rn(p.x, p.y);
        }
        __stcs(&out4[(size_t)(l0 + li) * B4 + b4],
               make_float4(o[0], o[1], o[2], o[3]));
    }

    // --- tail: last CTA of this b-quadrant re-zeroes its T slice + counter ---
    __syncthreads();
    __threadfence();
    if (t == 0) {
        int old = atomicAdd(&g_count[blockIdx.x], 1);
        s_last = (old == (int)gridDim.y - 1);
    }
    __syncthreads();
    if (s_last) {
        float4 z = make_float4(0.f, 0.f, 0.f, 0.f);
        float4* Tz = (float4*)g_T;
        #pragma unroll
        for (int r = 0; r < RANK; r++)
            Tz[r * B4 + b4] = z;
        __threadfence();
        if (t == 0) atomicExch(&g_count[blockIdx.x], 0);
    }
}

extern "C" void kernel_launch(void* const* d_in, const int* in_sizes, int n_in,
                              void* d_out, int out_size) {
    const float* inp = (const float*)d_in[0];  // [L, B]
    const float* U   = (const float*)d_in[1];  // [RANK, L]
    const float* V   = (const float*)d_in[2];  // [RANK, L]
    float* out = (float*)d_out;                // [L, B]

    dim3 g1(B4 / 256, M_SPLITS);
    vx_kernel<<<g1, 256>>>(inp, V);

    dim3 g2(B4 / 256, L_DIM / L_TILE);
    out_kernel<<<g2, 256>>>(U, out);
}